// round 6
// baseline (speedup 1.0000x reference)
#include <cuda_runtime.h>
#include <math.h>
#include <cstdint>

// Fixed shape: query_len = key_len = 2048, 8 fp32 channels, TRUNC = 200.
#define QL 2048
#define KL 2048
#define NT 201              // distinct T values 0..200 (T>200 -> T=0 vector)
#define THREADS 256
#define CONST_PIX 1024      // const-region staging buffer: 1024 px = 32 KB
#define BAND_MAX 416        // band is <= 401 px; padded

__device__ __forceinline__ uint32_t smem_u32(const void* p) {
    uint32_t a;
    asm("{ .reg .u64 t; cvta.to.shared.u64 t, %1; cvt.u32.u64 %0, t; }"
        : "=r"(a) : "l"(p));
    return a;
}

__device__ __forceinline__ void bulk_s2g(float4* g, uint32_t s, int bytes) {
    asm volatile("cp.async.bulk.global.shared::cta.bulk_group [%0], [%1], %2;"
                 :: "l"(g), "r"(s), "r"(bytes) : "memory");
}

// One CTA = one output row (2048 px = 64 KB).
// Dual-path stores: ~37% of the constant far region goes out via direct STG
// (3.8 TB/s wall, R1/R2) from 255 threads, concurrently with TMA bulk copies
// (5.8 TB/s wall, R3/R4) issued by tid 0. If the two store paths are even
// partially independent, combined throughput beats either alone.
__global__ __launch_bounds__(THREADS) void fill_row_kernel(
    const float* __restrict__ eta, const float* __restrict__ nu,
    const float* __restrict__ theta, float4* __restrict__ out)
{
    __shared__ __align__(16) float4 cbuf[CONST_PIX * 2];  // 32 KB, constant
    __shared__ __align__(16) float4 bbuf[BAND_MAX * 2];   // 13 KB, band
    __shared__ __align__(16) float4 lut[2 * NT];          // 6.4 KB

    const int tid = threadIdx.x;
    const int i = blockIdx.x;                 // row index

    const float4 farA = make_float4(1.f, 1.f, 0.f, 0.f);
    const float4 farB = make_float4(1.f, 1.f, 1.f, 0.f);

    // ---- fill constant TMA source buffer ----
#pragma unroll
    for (int k = 0; k < (CONST_PIX * 2) / THREADS; k++) {
        int f = tid + k * THREADS;
        cbuf[f] = (f & 1) ? farB : farA;
    }

    // ---- build LUT (all fp32; rel_err ~4e-9 verified R2-R5) ----
    if (tid < NT) {
        float lambda = tanhf(eta[0]);
        float gamma  = 1.0f / (1.0f + expf(-nu[0]));
        float th     = theta[0];
        float T      = (float)tid;

        float gT = powf(gamma, T);
        float s, c;  sincosf(T * th, &s, &c);
        float v0 = gT * c;            // ch0, ch1
        float v2 = gT * s;            // ch2, ch3

        float L2d = (tid % 2  == 0) ? T * 0.5f    : 0.0f;
        float L4d = (tid % 4  == 0) ? T * 0.25f   : 0.0f;
        float L8d = (tid % 8  == 0) ? T * 0.125f  : 0.0f;
        float L16 = (tid % 16 == 0) ? T * 0.0625f : 0.0f;

        float v4 = powf(lambda, L2d);                   // ch4
        float v5 = powf(lambda, L4d);                   // ch5
        float s8, c8;   sincosf(L8d * th, &s8, &c8);
        float s16, c16; sincosf(L16 * th, &s16, &c16);
        float v6 = powf(gamma, L8d) * c8;               // ch6
        float v7 = powf(gamma, L16) * s16;              // ch7

        lut[2 * tid]     = make_float4(v0, v0, v2, v2);
        lut[2 * tid + 1] = make_float4(v4, v5, v6, v7);
    }
    __syncthreads();

    const int jlo = (i - 200 > 0) ? i - 200 : 0;
    const int jhi = (i + 200 < KL - 1) ? i + 200 : KL - 1;
    const int npix = jhi - jlo + 1;                   // <= 401
    float4* rowp = out + (size_t)i * (2 * KL);

    // Far segments: left [0, jlo), right [jhi+1, KL).
    // Each segment: first stg_len px via direct STG, rest via TMA.
    // STG share = 3/8 (~rate ratio 3.8 : 5.8), rounded to 16px (512B).
    const int segA[2]   = {0, jhi + 1};
    const int segLen[2] = {jlo, KL - (jhi + 1)};
    int stgLen[2], tmaA[2], tmaLen[2];
#pragma unroll
    for (int s = 0; s < 2; s++) {
        stgLen[s] = (segLen[s] * 3 / 8) & ~15;
        tmaA[s]   = segA[s] + stgLen[s];
        tmaLen[s] = segLen[s] - stgLen[s];
    }

    // ---- tid 0: post all far-region TMA copies immediately ----
    if (tid == 0) {
        asm volatile("fence.proxy.async.shared::cta;" ::: "memory");
        const uint32_t cb = smem_u32(cbuf);
#pragma unroll
        for (int s = 0; s < 2; s++) {
            int rem = tmaLen[s], off = tmaA[s];
            while (rem > 0) {
                int n = (rem < CONST_PIX) ? rem : CONST_PIX;
                bulk_s2g(rowp + 2 * off, cb, n * 32);
                off += n; rem -= n;
            }
        }
        asm volatile("cp.async.bulk.commit_group;" ::: "memory");
    }

    // ---- all threads: STG the constant share (no loads, no SMEM) ----
#pragma unroll
    for (int s = 0; s < 2; s++) {
        const int f0 = 2 * segA[s];
        const int f1 = f0 + 2 * stgLen[s];
        for (int f = f0 + tid; f < f1; f += THREADS)
            rowp[f] = (f & 1) ? farB : farA;
    }

    // ---- fill band buffer (<=401 px, T = |i-j| <= 200 by construction) ----
    for (int k = tid; k < npix; k += THREADS) {
        int j = jlo + k;
        int T = i - j;  T = (T < 0) ? -T : T;
        bbuf[2 * k]     = lut[2 * T];
        bbuf[2 * k + 1] = lut[2 * T + 1];
    }
    __syncthreads();

    // ---- band copy + drain ----
    if (tid == 0) {
        asm volatile("fence.proxy.async.shared::cta;" ::: "memory");
        bulk_s2g(rowp + 2 * jlo, smem_u32(bbuf), npix * 32);
        asm volatile("cp.async.bulk.commit_group;" ::: "memory");
        asm volatile("cp.async.bulk.wait_group 0;" ::: "memory");
    }
}

extern "C" void kernel_launch(void* const* d_in, const int* in_sizes, int n_in,
                              void* d_out, int out_size) {
    const float* eta   = (const float*)d_in[0];
    const float* nu    = (const float*)d_in[1];
    const float* theta = (const float*)d_in[2];

    fill_row_kernel<<<QL, THREADS>>>(eta, nu, theta, (float4*)d_out);
}